// round 14
// baseline (speedup 1.0000x reference)
#include <cuda_runtime.h>
#include <math.h>

#define SS 64
#define S3 (SS*SS*SS)

typedef unsigned long long u64;

// Scratch (allocation-free)
__device__ float g_hidden[64 * S3];      // [64][z][y][x]
__device__ float g_w1t[16 * 27 * 64];    // [ic][k][oc]   (oc-vector form)
__device__ float g_w2t[64 * 27 * 16];    // [ic][k][oc]   (oc-vector form)

__device__ __forceinline__ u64 pack2(float x) {
    u64 r; asm("mov.b64 %0, {%1, %1};" : "=l"(r) : "f"(x)); return r;
}
__device__ __forceinline__ void unpack2(u64 v, float& lo, float& hi) {
    asm("mov.b64 {%0, %1}, %2;" : "=f"(lo), "=f"(hi) : "l"(v));
}
__device__ __forceinline__ u64 fma2(u64 a, u64 b, u64 c) {
    u64 d; asm("fma.rn.f32x2 %0, %1, %2, %3;" : "=l"(d) : "l"(a), "l"(b), "l"(c)); return d;
}
__device__ __forceinline__ float tanh_fast(float x) {
    float y; asm("tanh.approx.f32 %0, %1;" : "=f"(y) : "f"(x)); return y;
}

// ---------------------------------------------------------------------------
// Weight transposes
// ---------------------------------------------------------------------------
__global__ void transpose_w1(const float* __restrict__ w1) {
    int idx = blockIdx.x * 256 + threadIdx.x;
    if (idx < 16 * 27 * 64) {
        int oc = idx & 63; int r = idx >> 6; int k = r % 27; int ic = r / 27;
        g_w1t[idx] = w1[(oc * 16 + ic) * 27 + k];
    }
}
// w2 [16][64][27] -> g_w2t [ic][k][oc]
__global__ void transpose_w2(const float* __restrict__ w2) {
    int idx = blockIdx.x * 256 + threadIdx.x;
    if (idx < 64 * 27 * 16) {
        int oc = idx & 15; int r = idx >> 4; int k = r % 27; int ic = r / 27;
        g_w2t[idx] = w2[(oc * 64 + ic) * 27 + k];
    }
}

// ---------------------------------------------------------------------------
// Kernel A: hidden = tanh(conv3d(y, w1) + b1)      (unchanged — at mix bound)
// Tile 8z x 4y x 8x, 64 oc. 512 threads.
// ---------------------------------------------------------------------------
#define C1_PAD 24
#define C1_SINF (16 * 10 * 6 * C1_PAD)   // 23040 floats
#define C1_SWF  (16 * 27 * 64)           // 27648 floats
__global__ __launch_bounds__(512, 1)
void conv1_kernel(const float* __restrict__ y, const float* __restrict__ b1) {
    extern __shared__ float sm[];
    float* s_w  = sm;            // [16][27][64]
    float* s_in = sm + C1_SWF;   // [16][10z][6y][24 pad] (10 real x values)

    const int tid = threadIdx.x;
    const int x0 = blockIdx.x * 8;
    const int y0 = blockIdx.y * 4;
    const int z0 = blockIdx.z * 8;

    {   // stage weights (float4 coalesced)
        const float4* src = (const float4*)g_w1t;
        float4* dst = (float4*)s_w;
        for (int i = tid; i < C1_SWF / 4; i += 512) dst[i] = src[i];
    }
    // stage input halo tile: 16ic x 10z x 6y x 10x
    for (int idx = tid; idx < 16 * 10 * 6 * 10; idx += 512) {
        int xx = idx % 10;
        int r = idx / 10;
        int yy = r % 6; r /= 6;
        int zz = r % 10; int ic = r / 10;
        float v = 0.f;
        int gx = x0 + xx - 1, gy = y0 + yy - 1, gz = z0 + zz - 1;
        if ((unsigned)gx < SS && (unsigned)gy < SS && (unsigned)gz < SS)
            v = y[((ic * SS + gz) * SS + gy) * SS + gx];
        s_in[((ic * 10 + zz) * 6 + yy) * C1_PAD + xx] = v;
    }
    __syncthreads();

    const int og = tid >> 6;
    const int r  = tid & 63;
    const int xh = r & 1;
    const int ly = (r >> 1) & 3;
    const int lz = r >> 3;

    u64 acc[4][4];   // [voxel][oc-pair]
    #pragma unroll
    for (int v = 0; v < 4; v++)
        #pragma unroll
        for (int p = 0; p < 4; p++) acc[v][p] = 0ull;

    for (int ic = 0; ic < 16; ic++) {
        const float* in_c = s_in + ic * (10 * 6 * C1_PAD) + xh * 4;
        const float* w_c  = s_w + ic * (27 * 64) + og * 8;
        #pragma unroll
        for (int kz = 0; kz < 3; kz++)
        #pragma unroll
        for (int ky = 0; ky < 3; ky++) {
            const float* rp = in_c + ((lz + kz) * 6 + (ly + ky)) * C1_PAD;
            float4 f0 = *(const float4*)rp;         // aligned, conflict-free
            float2 f1 = *(const float2*)(rp + 4);
            u64 P[6];
            P[0] = pack2(f0.x); P[1] = pack2(f0.y); P[2] = pack2(f0.z);
            P[3] = pack2(f0.w); P[4] = pack2(f1.x); P[5] = pack2(f1.y);
            #pragma unroll
            for (int kx = 0; kx < 3; kx++) {
                const ulonglong2* wp =
                    (const ulonglong2*)(w_c + ((kz * 3 + ky) * 3 + kx) * 64);
                ulonglong2 Wa = wp[0], Wb = wp[1];   // broadcast (uniform per warp)
                u64 W[4] = {Wa.x, Wa.y, Wb.x, Wb.y};
                #pragma unroll
                for (int v = 0; v < 4; v++)
                    #pragma unroll
                    for (int p = 0; p < 4; p++)
                        acc[v][p] = fma2(P[v + kx], W[p], acc[v][p]);
            }
        }
    }

    const int gz = z0 + lz, gy = y0 + ly, gx = x0 + xh * 4;
    #pragma unroll
    for (int p = 0; p < 4; p++) {
        const int oc0 = og * 8 + 2 * p;
        const float bb0 = b1[oc0], bb1 = b1[oc0 + 1];
        float4 o0, o1; float lo, hi;
        unpack2(acc[0][p], lo, hi); o0.x = tanh_fast(lo + bb0); o1.x = tanh_fast(hi + bb1);
        unpack2(acc[1][p], lo, hi); o0.y = tanh_fast(lo + bb0); o1.y = tanh_fast(hi + bb1);
        unpack2(acc[2][p], lo, hi); o0.z = tanh_fast(lo + bb0); o1.z = tanh_fast(hi + bb1);
        unpack2(acc[3][p], lo, hi); o0.w = tanh_fast(lo + bb0); o1.w = tanh_fast(hi + bb1);
        *(float4*)&g_hidden[((oc0 * SS + gz) * SS + gy) * SS + gx] = o0;
        *(float4*)&g_hidden[(((oc0 + 1) * SS + gz) * SS + gy) * SS + gx] = o1;
    }
}

// ---------------------------------------------------------------------------
// Kernel B (R11 inner structure, repacked for 4 CTAs/SM + balanced grid):
//   y += (conv3d(hidden, w2) + b2)*dt + sigma*sqrt(dt)*noise
// Tile 8z x 8y x 8x = 512 vox, 16 oc. 128 threads, 4 CTAs/SM.
// Each thread: 4 x-consecutive voxels x ALL 16 oc (8 oc-pairs, 32 u64 accs).
// Lane map: xh=vg&1, ly=(vg>>1)&7, lz=vg>>4  (pad-24 conflict-free, as R11).
// ic chunked x4 through smem (16 chunks).
// ---------------------------------------------------------------------------
#define C2_PAD 24
#define C2_ICC 4
#define C2_SINF (C2_ICC * 10 * 10 * C2_PAD)   // 9600 floats
#define C2_SWF  (C2_ICC * 27 * 16)            // 1728 floats
__global__ __launch_bounds__(128, 4)
void conv2_kernel(float* __restrict__ y, const float* __restrict__ b2,
                  const float* __restrict__ noise) {
    extern __shared__ float sm[];
    float* s_w  = sm;            // [4][27][16]
    float* s_in = sm + C2_SWF;   // [4][10z][10y][24 pad] (10 real x values)

    const int tid = threadIdx.x;
    const int x0 = blockIdx.x * 8;
    const int y0 = blockIdx.y * 8;
    const int z0 = blockIdx.z * 8;

    const int xh = tid & 1;
    const int ly = (tid >> 1) & 7;
    const int lz = tid >> 4;

    u64 acc[4][8];   // [voxel][oc-pair]
    #pragma unroll
    for (int v = 0; v < 4; v++)
        #pragma unroll
        for (int p = 0; p < 8; p++) acc[v][p] = 0ull;

    for (int chunk = 0; chunk < 16; chunk++) {
        const int icg = chunk * C2_ICC;
        __syncthreads();
        {   // stage this chunk's weights: 1728 floats = 432 float4
            const float4* src = (const float4*)(g_w2t + icg * 27 * 16);
            float4* dst = (float4*)s_w;
            for (int i = tid; i < C2_SWF / 4; i += 128) dst[i] = src[i];
        }
        // stage input chunk: 4ic x 10z x 10y x 10x = 4000 elems
        for (int idx = tid; idx < C2_ICC * 10 * 10 * 10; idx += 128) {
            int xx = idx % 10;
            int r = idx / 10;
            int yy = r % 10; r /= 10;
            int zz = r % 10; int ic = r / 10;
            float v = 0.f;
            int gx = x0 + xx - 1, gy = y0 + yy - 1, gz = z0 + zz - 1;
            if ((unsigned)gx < SS && (unsigned)gy < SS && (unsigned)gz < SS)
                v = g_hidden[(((icg + ic) * SS + gz) * SS + gy) * SS + gx];
            s_in[((ic * 10 + zz) * 10 + yy) * C2_PAD + xx] = v;
        }
        __syncthreads();

        #pragma unroll
        for (int ic = 0; ic < C2_ICC; ic++) {
            const float* in_c = s_in + ic * (10 * 10 * C2_PAD) + xh * 4;
            const float* w_c  = s_w + ic * (27 * 16);
            #pragma unroll
            for (int kz = 0; kz < 3; kz++)
            #pragma unroll
            for (int ky = 0; ky < 3; ky++) {
                const float* rp = in_c + ((lz + kz) * 10 + (ly + ky)) * C2_PAD;
                float4 f0 = *(const float4*)rp;        // conflict-free (pad 24)
                float2 f1 = *(const float2*)(rp + 4);
                u64 P[6];
                P[0] = pack2(f0.x); P[1] = pack2(f0.y); P[2] = pack2(f0.z);
                P[3] = pack2(f0.w); P[4] = pack2(f1.x); P[5] = pack2(f1.y);
                #pragma unroll
                for (int kx = 0; kx < 3; kx++) {
                    const ulonglong2* wp =
                        (const ulonglong2*)(w_c + ((kz * 3 + ky) * 3 + kx) * 16);
                    ulonglong2 wA = wp[0], wB = wp[1];  // broadcast (uniform per warp)
                    u64 W[4] = {wA.x, wA.y, wB.x, wB.y};
                    #pragma unroll
                    for (int v = 0; v < 4; v++)
                        #pragma unroll
                        for (int p = 0; p < 4; p++)
                            acc[v][p] = fma2(P[v + kx], W[p], acc[v][p]);
                    const ulonglong2* wq = wp + 2;
                    ulonglong2 wC = wq[0], wD = wq[1];
                    u64 W2[4] = {wC.x, wC.y, wD.x, wD.y};
                    #pragma unroll
                    for (int v = 0; v < 4; v++)
                        #pragma unroll
                        for (int p = 0; p < 4; p++)
                            acc[v][4 + p] = fma2(P[v + kx], W2[p], acc[v][4 + p]);
                }
            }
        }
    }

    const int gz = z0 + lz, gy = y0 + ly, gx = x0 + xh * 4;
    const float dt  = 0.05f;
    const float sdt = 0.1f * 0.22360680f;   // sigma * sqrt(dt)
    #pragma unroll
    for (int p = 0; p < 8; p++) {
        const int oc0 = 2 * p;
        const float bb0 = b2[oc0], bb1 = b2[oc0 + 1];
        const int base0 = ((oc0 * SS + gz) * SS + gy) * SS + gx;
        const int base1 = (((oc0 + 1) * SS + gz) * SS + gy) * SS + gx;
        float4 y0v = *(const float4*)&y[base0];
        float4 y1v = *(const float4*)&y[base1];
        float4 n0v = *(const float4*)&noise[base0];
        float4 n1v = *(const float4*)&noise[base1];
        float lo, hi;
        unpack2(acc[0][p], lo, hi);
        y0v.x += (lo + bb0) * dt + sdt * n0v.x; y1v.x += (hi + bb1) * dt + sdt * n1v.x;
        unpack2(acc[1][p], lo, hi);
        y0v.y += (lo + bb0) * dt + sdt * n0v.y; y1v.y += (hi + bb1) * dt + sdt * n1v.y;
        unpack2(acc[2][p], lo, hi);
        y0v.z += (lo + bb0) * dt + sdt * n0v.z; y1v.z += (hi + bb1) * dt + sdt * n1v.z;
        unpack2(acc[3][p], lo, hi);
        y0v.w += (lo + bb0) * dt + sdt * n0v.w; y1v.w += (hi + bb1) * dt + sdt * n1v.w;
        *(float4*)&y[base0] = y0v;
        *(float4*)&y[base1] = y1v;
    }
}

// ---------------------------------------------------------------------------
// Launch: y(d_out) <- x; 20x { conv1 -> conv2(update) }. Graph-capturable.
// ---------------------------------------------------------------------------
extern "C" void kernel_launch(void* const* d_in, const int* in_sizes, int n_in,
                              void* d_out, int out_size) {
    const float* x     = (const float*)d_in[0];
    // d_in[1] = integration_time (ts = [0,1], N_STEPS = 20 fixed)
    const float* w1    = (const float*)d_in[2];
    const float* b1    = (const float*)d_in[3];
    const float* w2    = (const float*)d_in[4];
    const float* b2    = (const float*)d_in[5];
    const float* noise = (const float*)d_in[6];
    float* y = (float*)d_out;

    const size_t smA = (size_t)(C1_SWF + C1_SINF) * sizeof(float);  // 202.75 KB
    const size_t smB = (size_t)(C2_SWF + C2_SINF) * sizeof(float);  // 45.3 KB
    cudaFuncSetAttribute(conv1_kernel, cudaFuncAttributeMaxDynamicSharedMemorySize, (int)smA);
    cudaFuncSetAttribute(conv2_kernel, cudaFuncAttributeMaxDynamicSharedMemorySize, (int)smB);

    cudaMemcpyAsync(y, x, (size_t)16 * S3 * sizeof(float), cudaMemcpyDeviceToDevice);
    transpose_w1<<<108, 256>>>(w1);
    transpose_w2<<<108, 256>>>(w2);

    dim3 gA(8, 16, 8);   // x/8, y/4, z/8   = 1024 CTAs
    dim3 gB(8, 8, 8);    // x/8, y/8, z/8   = 1024 CTAs
    for (int step = 0; step < 20; step++) {
        conv1_kernel<<<gA, 512, smA>>>(y, b1);
        conv2_kernel<<<gB, 128, smB>>>(y, b2, noise + (size_t)step * 16 * S3);
    }
}

// round 15
// speedup vs baseline: 1.5796x; 1.5796x over previous
#include <cuda_runtime.h>
#include <math.h>

#define SS 64
#define S3 (SS*SS*SS)

typedef unsigned long long u64;

// Scratch (allocation-free)
__device__ float g_hidden[64 * S3];      // [64][z][y][x]
__device__ float g_w1t[16 * 27 * 64];    // [ic][k][oc]   (oc-vector form)
__device__ float g_w2t[64 * 27 * 16];    // [ic][k][oc]   (oc-vector form)

__device__ __forceinline__ u64 pack2(float x) {
    u64 r; asm("mov.b64 %0, {%1, %1};" : "=l"(r) : "f"(x)); return r;
}
__device__ __forceinline__ void unpack2(u64 v, float& lo, float& hi) {
    asm("mov.b64 {%0, %1}, %2;" : "=f"(lo), "=f"(hi) : "l"(v));
}
__device__ __forceinline__ u64 fma2(u64 a, u64 b, u64 c) {
    u64 d; asm("fma.rn.f32x2 %0, %1, %2, %3;" : "=l"(d) : "l"(a), "l"(b), "l"(c)); return d;
}
__device__ __forceinline__ float tanh_fast(float x) {
    float y; asm("tanh.approx.f32 %0, %1;" : "=f"(y) : "f"(x)); return y;
}

// ---------------------------------------------------------------------------
// Weight transposes
// ---------------------------------------------------------------------------
__global__ void transpose_w1(const float* __restrict__ w1) {
    int idx = blockIdx.x * 256 + threadIdx.x;
    if (idx < 16 * 27 * 64) {
        int oc = idx & 63; int r = idx >> 6; int k = r % 27; int ic = r / 27;
        g_w1t[idx] = w1[(oc * 16 + ic) * 27 + k];
    }
}
// w2 [16][64][27] -> g_w2t [ic][k][oc]
__global__ void transpose_w2(const float* __restrict__ w2) {
    int idx = blockIdx.x * 256 + threadIdx.x;
    if (idx < 64 * 27 * 16) {
        int oc = idx & 15; int r = idx >> 4; int k = r % 27; int ic = r / 27;
        g_w2t[idx] = w2[(oc * 64 + ic) * 27 + k];
    }
}

// ---------------------------------------------------------------------------
// Kernel A: hidden = tanh(conv3d(y, w1) + b1)      (unchanged — at mix bound)
// Tile 8z x 4y x 8x, 64 oc. 512 threads.
// ---------------------------------------------------------------------------
#define C1_PAD 24
#define C1_SINF (16 * 10 * 6 * C1_PAD)   // 23040 floats
#define C1_SWF  (16 * 27 * 64)           // 27648 floats
__global__ __launch_bounds__(512, 1)
void conv1_kernel(const float* __restrict__ y, const float* __restrict__ b1) {
    extern __shared__ float sm[];
    float* s_w  = sm;            // [16][27][64]
    float* s_in = sm + C1_SWF;   // [16][10z][6y][24 pad] (10 real x values)

    const int tid = threadIdx.x;
    const int x0 = blockIdx.x * 8;
    const int y0 = blockIdx.y * 4;
    const int z0 = blockIdx.z * 8;

    {   // stage weights (float4 coalesced)
        const float4* src = (const float4*)g_w1t;
        float4* dst = (float4*)s_w;
        for (int i = tid; i < C1_SWF / 4; i += 512) dst[i] = src[i];
    }
    // stage input halo tile: 16ic x 10z x 6y x 10x
    for (int idx = tid; idx < 16 * 10 * 6 * 10; idx += 512) {
        int xx = idx % 10;
        int r = idx / 10;
        int yy = r % 6; r /= 6;
        int zz = r % 10; int ic = r / 10;
        float v = 0.f;
        int gx = x0 + xx - 1, gy = y0 + yy - 1, gz = z0 + zz - 1;
        if ((unsigned)gx < SS && (unsigned)gy < SS && (unsigned)gz < SS)
            v = y[((ic * SS + gz) * SS + gy) * SS + gx];
        s_in[((ic * 10 + zz) * 6 + yy) * C1_PAD + xx] = v;
    }
    __syncthreads();

    const int og = tid >> 6;
    const int r  = tid & 63;
    const int xh = r & 1;
    const int ly = (r >> 1) & 3;
    const int lz = r >> 3;

    u64 acc[4][4];   // [voxel][oc-pair]
    #pragma unroll
    for (int v = 0; v < 4; v++)
        #pragma unroll
        for (int p = 0; p < 4; p++) acc[v][p] = 0ull;

    for (int ic = 0; ic < 16; ic++) {
        const float* in_c = s_in + ic * (10 * 6 * C1_PAD) + xh * 4;
        const float* w_c  = s_w + ic * (27 * 64) + og * 8;
        #pragma unroll
        for (int kz = 0; kz < 3; kz++)
        #pragma unroll
        for (int ky = 0; ky < 3; ky++) {
            const float* rp = in_c + ((lz + kz) * 6 + (ly + ky)) * C1_PAD;
            float4 f0 = *(const float4*)rp;         // aligned, conflict-free
            float2 f1 = *(const float2*)(rp + 4);
            u64 P[6];
            P[0] = pack2(f0.x); P[1] = pack2(f0.y); P[2] = pack2(f0.z);
            P[3] = pack2(f0.w); P[4] = pack2(f1.x); P[5] = pack2(f1.y);
            #pragma unroll
            for (int kx = 0; kx < 3; kx++) {
                const ulonglong2* wp =
                    (const ulonglong2*)(w_c + ((kz * 3 + ky) * 3 + kx) * 64);
                ulonglong2 Wa = wp[0], Wb = wp[1];   // broadcast (uniform per warp)
                u64 W[4] = {Wa.x, Wa.y, Wb.x, Wb.y};
                #pragma unroll
                for (int v = 0; v < 4; v++)
                    #pragma unroll
                    for (int p = 0; p < 4; p++)
                        acc[v][p] = fma2(P[v + kx], W[p], acc[v][p]);
            }
        }
    }

    const int gz = z0 + lz, gy = y0 + ly, gx = x0 + xh * 4;
    #pragma unroll
    for (int p = 0; p < 4; p++) {
        const int oc0 = og * 8 + 2 * p;
        const float bb0 = b1[oc0], bb1 = b1[oc0 + 1];
        float4 o0, o1; float lo, hi;
        unpack2(acc[0][p], lo, hi); o0.x = tanh_fast(lo + bb0); o1.x = tanh_fast(hi + bb1);
        unpack2(acc[1][p], lo, hi); o0.y = tanh_fast(lo + bb0); o1.y = tanh_fast(hi + bb1);
        unpack2(acc[2][p], lo, hi); o0.z = tanh_fast(lo + bb0); o1.z = tanh_fast(hi + bb1);
        unpack2(acc[3][p], lo, hi); o0.w = tanh_fast(lo + bb0); o1.w = tanh_fast(hi + bb1);
        *(float4*)&g_hidden[((oc0 * SS + gz) * SS + gy) * SS + gx] = o0;
        *(float4*)&g_hidden[(((oc0 + 1) * SS + gz) * SS + gy) * SS + gx] = o1;
    }
}

// ---------------------------------------------------------------------------
// Kernel B (R11 inner structure, repacked for 4 CTAs/SM + balanced grid):
//   y += (conv3d(hidden, w2) + b2)*dt + sigma*sqrt(dt)*noise
// Tile 8z x 8y x 8x = 512 vox, 16 oc. 128 threads, 4 CTAs/SM.
// Each thread: 4 x-consecutive voxels x ALL 16 oc (8 oc-pairs, 32 u64 accs).
// Lane map: xh=vg&1, ly=(vg>>1)&7, lz=vg>>4  (pad-24 conflict-free, as R11).
// ic chunked x4 through smem (16 chunks).
// ---------------------------------------------------------------------------
#define C2_PAD 24
#define C2_ICC 4
#define C2_SINF (C2_ICC * 10 * 10 * C2_PAD)   // 9600 floats
#define C2_SWF  (C2_ICC * 27 * 16)            // 1728 floats
__global__ __launch_bounds__(128, 4)
void conv2_kernel(float* __restrict__ y, const float* __restrict__ b2,
                  const float* __restrict__ noise) {
    extern __shared__ float sm[];
    float* s_w  = sm;            // [4][27][16]
    float* s_in = sm + C2_SWF;   // [4][10z][10y][24 pad] (10 real x values)

    const int tid = threadIdx.x;
    const int x0 = blockIdx.x * 8;
    const int y0 = blockIdx.y * 8;
    const int z0 = blockIdx.z * 8;

    const int xh = tid & 1;
    const int ly = (tid >> 1) & 7;
    const int lz = tid >> 4;

    u64 acc[4][8];   // [voxel][oc-pair]
    #pragma unroll
    for (int v = 0; v < 4; v++)
        #pragma unroll
        for (int p = 0; p < 8; p++) acc[v][p] = 0ull;

    for (int chunk = 0; chunk < 16; chunk++) {
        const int icg = chunk * C2_ICC;
        __syncthreads();
        {   // stage this chunk's weights: 1728 floats = 432 float4
            const float4* src = (const float4*)(g_w2t + icg * 27 * 16);
            float4* dst = (float4*)s_w;
            for (int i = tid; i < C2_SWF / 4; i += 128) dst[i] = src[i];
        }
        // stage input chunk: 4ic x 10z x 10y x 10x = 4000 elems
        for (int idx = tid; idx < C2_ICC * 10 * 10 * 10; idx += 128) {
            int xx = idx % 10;
            int r = idx / 10;
            int yy = r % 10; r /= 10;
            int zz = r % 10; int ic = r / 10;
            float v = 0.f;
            int gx = x0 + xx - 1, gy = y0 + yy - 1, gz = z0 + zz - 1;
            if ((unsigned)gx < SS && (unsigned)gy < SS && (unsigned)gz < SS)
                v = g_hidden[(((icg + ic) * SS + gz) * SS + gy) * SS + gx];
            s_in[((ic * 10 + zz) * 10 + yy) * C2_PAD + xx] = v;
        }
        __syncthreads();

        #pragma unroll
        for (int ic = 0; ic < C2_ICC; ic++) {
            const float* in_c = s_in + ic * (10 * 10 * C2_PAD) + xh * 4;
            const float* w_c  = s_w + ic * (27 * 16);
            #pragma unroll
            for (int kz = 0; kz < 3; kz++)
            #pragma unroll
            for (int ky = 0; ky < 3; ky++) {
                const float* rp = in_c + ((lz + kz) * 10 + (ly + ky)) * C2_PAD;
                float4 f0 = *(const float4*)rp;        // conflict-free (pad 24)
                float2 f1 = *(const float2*)(rp + 4);
                u64 P[6];
                P[0] = pack2(f0.x); P[1] = pack2(f0.y); P[2] = pack2(f0.z);
                P[3] = pack2(f0.w); P[4] = pack2(f1.x); P[5] = pack2(f1.y);
                #pragma unroll
                for (int kx = 0; kx < 3; kx++) {
                    const ulonglong2* wp =
                        (const ulonglong2*)(w_c + ((kz * 3 + ky) * 3 + kx) * 16);
                    ulonglong2 wA = wp[0], wB = wp[1];  // broadcast (uniform per warp)
                    u64 W[4] = {wA.x, wA.y, wB.x, wB.y};
                    #pragma unroll
                    for (int v = 0; v < 4; v++)
                        #pragma unroll
                        for (int p = 0; p < 4; p++)
                            acc[v][p] = fma2(P[v + kx], W[p], acc[v][p]);
                    const ulonglong2* wq = wp + 2;
                    ulonglong2 wC = wq[0], wD = wq[1];
                    u64 W2[4] = {wC.x, wC.y, wD.x, wD.y};
                    #pragma unroll
                    for (int v = 0; v < 4; v++)
                        #pragma unroll
                        for (int p = 0; p < 4; p++)
                            acc[v][4 + p] = fma2(P[v + kx], W2[p], acc[v][4 + p]);
                }
            }
        }
    }

    const int gz = z0 + lz, gy = y0 + ly, gx = x0 + xh * 4;
    const float dt  = 0.05f;
    const float sdt = 0.1f * 0.22360680f;   // sigma * sqrt(dt)
    #pragma unroll
    for (int p = 0; p < 8; p++) {
        const int oc0 = 2 * p;
        const float bb0 = b2[oc0], bb1 = b2[oc0 + 1];
        const int base0 = ((oc0 * SS + gz) * SS + gy) * SS + gx;
        const int base1 = (((oc0 + 1) * SS + gz) * SS + gy) * SS + gx;
        float4 y0v = *(const float4*)&y[base0];
        float4 y1v = *(const float4*)&y[base1];
        float4 n0v = *(const float4*)&noise[base0];
        float4 n1v = *(const float4*)&noise[base1];
        float lo, hi;
        unpack2(acc[0][p], lo, hi);
        y0v.x += (lo + bb0) * dt + sdt * n0v.x; y1v.x += (hi + bb1) * dt + sdt * n1v.x;
        unpack2(acc[1][p], lo, hi);
        y0v.y += (lo + bb0) * dt + sdt * n0v.y; y1v.y += (hi + bb1) * dt + sdt * n1v.y;
        unpack2(acc[2][p], lo, hi);
        y0v.z += (lo + bb0) * dt + sdt * n0v.z; y1v.z += (hi + bb1) * dt + sdt * n1v.z;
        unpack2(acc[3][p], lo, hi);
        y0v.w += (lo + bb0) * dt + sdt * n0v.w; y1v.w += (hi + bb1) * dt + sdt * n1v.w;
        *(float4*)&y[base0] = y0v;
        *(float4*)&y[base1] = y1v;
    }
}

// ---------------------------------------------------------------------------
// Launch: y(d_out) <- x; 20x { conv1 -> conv2(update) }. Graph-capturable.
// ---------------------------------------------------------------------------
extern "C" void kernel_launch(void* const* d_in, const int* in_sizes, int n_in,
                              void* d_out, int out_size) {
    const float* x     = (const float*)d_in[0];
    // d_in[1] = integration_time (ts = [0,1], N_STEPS = 20 fixed)
    const float* w1    = (const float*)d_in[2];
    const float* b1    = (const float*)d_in[3];
    const float* w2    = (const float*)d_in[4];
    const float* b2    = (const float*)d_in[5];
    const float* noise = (const float*)d_in[6];
    float* y = (float*)d_out;

    const size_t smA = (size_t)(C1_SWF + C1_SINF) * sizeof(float);  // 202.75 KB
    const size_t smB = (size_t)(C2_SWF + C2_SINF) * sizeof(float);  // 45.3 KB
    cudaFuncSetAttribute(conv1_kernel, cudaFuncAttributeMaxDynamicSharedMemorySize, (int)smA);
    cudaFuncSetAttribute(conv2_kernel, cudaFuncAttributeMaxDynamicSharedMemorySize, (int)smB);

    cudaMemcpyAsync(y, x, (size_t)16 * S3 * sizeof(float), cudaMemcpyDeviceToDevice);
    transpose_w1<<<108, 256>>>(w1);
    transpose_w2<<<108, 256>>>(w2);

    dim3 gA(8, 16, 8);   // x/8, y/4, z/8   = 1024 CTAs
    dim3 gB(8, 8, 8);    // x/8, y/8, z/8   = 1024 CTAs
    for (int step = 0; step < 20; step++) {
        conv1_kernel<<<gA, 512, smA>>>(y, b1);
        conv2_kernel<<<gB, 128, smB>>>(y, b2, noise + (size_t)step * 16 * S3);
    }
}

// round 16
// speedup vs baseline: 2.8953x; 1.8330x over previous
#include <cuda_runtime.h>
#include <cuda_bf16.h>

#define SS 64
#define S3 (SS*SS*SS)
typedef unsigned int u32;
typedef unsigned short u16;

// hidden state: bf16 hi/lo planes, ic-PAIR packed u32: [icp 32][vox S3]
__device__ u32 g_hid_hi[32 * S3];
__device__ u32 g_hid_lo[32 * S3];
__device__ u32 g_w1h[27 * 64 * 12];        // [tap][oc 64][24 bf16: 16 ic + pad]
__device__ u32 g_w1l[27 * 64 * 12];
__device__ u32 g_w2h[3 * 2 * 9 * 16 * 20]; // [dz][icc 2][t 9][oc 16][40 bf16: 32 ic + pad]
__device__ u32 g_w2l[3 * 2 * 9 * 16 * 20];

__device__ __forceinline__ float tanh_fast(float x) {
    float y; asm("tanh.approx.f32 %0, %1;" : "=f"(y) : "f"(x)); return y;
}
__device__ __forceinline__ void bsplit(float x, u16& h, u16& l) {
    __nv_bfloat16 bh = __float2bfloat16_rn(x);
    __nv_bfloat16 bl = __float2bfloat16_rn(x - __bfloat162float(bh));
    h = __bfloat16_as_ushort(bh); l = __bfloat16_as_ushort(bl);
}
__device__ __forceinline__ u32 pk(u16 lo, u16 hi) { return (u32)lo | ((u32)hi << 16); }
__device__ __forceinline__ void mma16(float* d, const u32* a, u32 b0, u32 b1) {
    asm volatile(
        "mma.sync.aligned.m16n8k16.row.col.f32.bf16.bf16.f32 "
        "{%0,%1,%2,%3}, {%4,%5,%6,%7}, {%8,%9}, {%0,%1,%2,%3};"
        : "+f"(d[0]), "+f"(d[1]), "+f"(d[2]), "+f"(d[3])
        : "r"(a[0]), "r"(a[1]), "r"(a[2]), "r"(a[3]), "r"(b0), "r"(b1));
}

__global__ void prep_w1(const float* __restrict__ w1) {   // [64 oc][16 ic][27]
    int idx = blockIdx.x * 256 + threadIdx.x;
    if (idx >= 27 * 64 * 24) return;
    int c = idx % 24, oc = (idx / 24) % 64, tap = idx / 1536;
    float v = (c < 16) ? w1[(oc * 16 + c) * 27 + tap] : 0.f;
    u16 h, l; bsplit(v, h, l);
    ((u16*)g_w1h)[idx] = h; ((u16*)g_w1l)[idx] = l;
}
__global__ void prep_w2(const float* __restrict__ w2) {   // [16 oc][64 ic][27]
    int idx = blockIdx.x * 256 + threadIdx.x;
    if (idx >= 3 * 2 * 9 * 16 * 40) return;
    int c = idx % 40, oc = (idx / 40) % 16, tt = (idx / 640) % 9;
    int icc = (idx / 5760) % 2, dz = idx / 11520;
    float v = (c < 32) ? w2[(oc * 64 + icc * 32 + c) * 27 + dz * 9 + tt] : 0.f;
    u16 h, l; bsplit(v, h, l);
    ((u16*)g_w2h)[idx] = h; ((u16*)g_w2l)[idx] = l;
}

#define AW 408   // act smem row stride (408 % 32 = 24 -> conflict-free frag loads)

// ---------------------------------------------------------------------------
// conv1: hidden = tanh(conv3d(y, w1) + b1).  CTA 256 thr, tile 2z x 8y x 8x.
// M = 64 oc (4 m-tiles), N = 128 vox (16 n-tiles). warp: mh=w&1 -> m-tiles
// {2mh,2mh+1}; nh=w>>1 -> n-tiles {4nh..+3}. 27 taps, K=16 (ic), x3 split.
// ---------------------------------------------------------------------------
__global__ __launch_bounds__(256, 2)
void conv1_mma(const float* __restrict__ y, const float* __restrict__ b1) {
    extern __shared__ u32 sm[];
    u32* swh = sm;              // 9*64*12 = 6912
    u32* swl = sm + 6912;
    u32* sah = sm + 13824;      // 8 icp * 408
    u32* sal = sm + 17088;      // total 20352 u32

    const int tid = threadIdx.x;
    const int x0 = blockIdx.x * 8, y0 = blockIdx.y * 8, z0 = blockIdx.z * 2;
    const int lane = tid & 31, warp = tid >> 5;
    const int g = lane >> 2, tig = lane & 3;
    const int mh = warp & 1, nh = warp >> 1;

    // stage acts: 8 icp x (4z x 10y x 10x = 400) halo, hi/lo split
    for (int idx = tid; idx < 8 * 400; idx += 256) {
        int icp = idx / 400, v = idx % 400;
        int hz = v / 100, rem = v % 100, hy = rem / 10, hx = rem % 10;
        int gz = z0 + hz - 1, gy = y0 + hy - 1, gx = x0 + hx - 1;
        float v0 = 0.f, v1 = 0.f;
        if ((unsigned)gz < SS && (unsigned)gy < SS && (unsigned)gx < SS) {
            int b = (gz * SS + gy) * SS + gx;
            v0 = y[(2 * icp) * S3 + b]; v1 = y[(2 * icp + 1) * S3 + b];
        }
        u16 h0, l0, h1, l1; bsplit(v0, h0, l0); bsplit(v1, h1, l1);
        sah[icp * AW + v] = pk(h0, h1); sal[icp * AW + v] = pk(l0, l1);
    }

    float d[2][4][4];
    #pragma unroll
    for (int mi = 0; mi < 2; mi++)
        #pragma unroll
        for (int ni = 0; ni < 4; ni++)
            { d[mi][ni][0]=0.f; d[mi][ni][1]=0.f; d[mi][ni][2]=0.f; d[mi][ni][3]=0.f; }

    for (int dz = 0; dz < 3; dz++) {
        __syncthreads();
        {   // stage 9-tap weight slab for this dz (uint4 copies)
            const uint4* sh = (const uint4*)(g_w1h + dz * 6912);
            const uint4* sl = (const uint4*)(g_w1l + dz * 6912);
            uint4* dh = (uint4*)swh; uint4* dl = (uint4*)swl;
            for (int i = tid; i < 1728; i += 256) { dh[i] = sh[i]; dl[i] = sl[i]; }
        }
        __syncthreads();
        #pragma unroll
        for (int dy = 0; dy < 3; dy++)
        #pragma unroll
        for (int dx = 0; dx < 3; dx++) {
            const int t = dy * 3 + dx;
            u32 ah[2][4], al[2][4];
            #pragma unroll
            for (int mi = 0; mi < 2; mi++) {
                int base = t * 768 + ((mh * 2 + mi) * 16 + g) * 12;
                ah[mi][0] = swh[base + tig];       ah[mi][1] = swh[base + 96 + tig];
                ah[mi][2] = swh[base + 4 + tig];   ah[mi][3] = swh[base + 100 + tig];
                al[mi][0] = swl[base + tig];       al[mi][1] = swl[base + 96 + tig];
                al[mi][2] = swl[base + 4 + tig];   al[mi][3] = swl[base + 100 + tig];
            }
            #pragma unroll
            for (int ni = 0; ni < 4; ni++) {
                int nt = nh * 4 + ni;
                int h = (((nt >> 3) + dz) * 10 + (nt & 7) + dy) * 10 + g + dx;
                u32 bh0 = sah[tig * AW + h], bh1 = sah[(tig + 4) * AW + h];
                u32 bl0 = sal[tig * AW + h], bl1 = sal[(tig + 4) * AW + h];
                #pragma unroll
                for (int mi = 0; mi < 2; mi++) {
                    mma16(d[mi][ni], ah[mi], bh0, bh1);
                    mma16(d[mi][ni], ah[mi], bl0, bl1);
                    mma16(d[mi][ni], al[mi], bh0, bh1);
                }
            }
        }
    }

    // epilogue: bias+tanh, pack ic-pairs via shfl, store hidden planes
    #pragma unroll
    for (int mi = 0; mi < 2; mi++) {
        const int oc = (mh * 2 + mi) * 16 + g;
        const float bb0 = b1[oc], bb1 = b1[oc + 8];
        #pragma unroll
        for (int ni = 0; ni < 4; ni++) {
            int nt = nh * 4 + ni;
            int gvox = ((z0 + (nt >> 3)) * SS + (y0 + (nt & 7))) * SS + x0 + 2 * tig;
            float t0 = tanh_fast(d[mi][ni][0] + bb0);
            float t1 = tanh_fast(d[mi][ni][1] + bb0);
            float t2 = tanh_fast(d[mi][ni][2] + bb1);
            float t3 = tanh_fast(d[mi][ni][3] + bb1);
            float p0 = __shfl_down_sync(0xffffffffu, t0, 4);
            float p1 = __shfl_down_sync(0xffffffffu, t1, 4);
            float p2 = __shfl_down_sync(0xffffffffu, t2, 4);
            float p3 = __shfl_down_sync(0xffffffffu, t3, 4);
            if (!(g & 1)) {   // even oc pairs with oc+1 (lane+4)
                int icp0 = oc >> 1, icp8 = icp0 + 4;
                u16 ha, la, hb, lb; uint2 wh, wl;
                bsplit(t0, ha, la); bsplit(p0, hb, lb);
                wh.x = pk(ha, hb); wl.x = pk(la, lb);
                bsplit(t1, ha, la); bsplit(p1, hb, lb);
                wh.y = pk(ha, hb); wl.y = pk(la, lb);
                *(uint2*)&g_hid_hi[icp0 * S3 + gvox] = wh;
                *(uint2*)&g_hid_lo[icp0 * S3 + gvox] = wl;
                bsplit(t2, ha, la); bsplit(p2, hb, lb);
                wh.x = pk(ha, hb); wl.x = pk(la, lb);
                bsplit(t3, ha, la); bsplit(p3, hb, lb);
                wh.y = pk(ha, hb); wl.y = pk(la, lb);
                *(uint2*)&g_hid_hi[icp8 * S3 + gvox] = wh;
                *(uint2*)&g_hid_lo[icp8 * S3 + gvox] = wl;
            }
        }
    }
}

// ---------------------------------------------------------------------------
// conv2: y += (conv3d(hidden, w2)+b2)*dt + sdt*noise.  CTA 256 thr, same tile.
// M = 16 oc (1 m-tile), N = 128 vox. warp w: n-tiles {2w,2w+1}.
// K = 64 ic: icc chunks x2, 2 k-steps per tap. x3 split.
// ---------------------------------------------------------------------------
__global__ __launch_bounds__(256, 2)
void conv2_mma(float* __restrict__ y, const float* __restrict__ b2,
               const float* __restrict__ noise) {
    extern __shared__ u32 sm[];
    u32* swh = sm;              // 9*16*20 = 2880
    u32* swl = sm + 2880;
    u32* sbh = sm + 5760;       // 16 icp * 408
    u32* sbl = sm + 12288;      // total 18816 u32

    const int tid = threadIdx.x;
    const int x0 = blockIdx.x * 8, y0 = blockIdx.y * 8, z0 = blockIdx.z * 2;
    const int lane = tid & 31, warp = tid >> 5;
    const int g = lane >> 2, tig = lane & 3;

    float d[2][4];
    #pragma unroll
    for (int ni = 0; ni < 2; ni++)
        { d[ni][0]=0.f; d[ni][1]=0.f; d[ni][2]=0.f; d[ni][3]=0.f; }

    for (int icc = 0; icc < 2; icc++) {
        __syncthreads();
        // stage act chunk: 16 icp x 400 halo (pure u32 copies of pair planes)
        for (int idx = tid; idx < 16 * 400; idx += 256) {
            int icp = idx / 400, v = idx % 400;
            int hz = v / 100, rem = v % 100, hy = rem / 10, hx = rem % 10;
            int gz = z0 + hz - 1, gy = y0 + hy - 1, gx = x0 + hx - 1;
            u32 wh = 0, wl = 0;
            if ((unsigned)gz < SS && (unsigned)gy < SS && (unsigned)gx < SS) {
                int b = (icc * 16 + icp) * S3 + (gz * SS + gy) * SS + gx;
                wh = g_hid_hi[b]; wl = g_hid_lo[b];
            }
            sbh[icp * AW + v] = wh; sbl[icp * AW + v] = wl;
        }
        for (int dz = 0; dz < 3; dz++) {
            __syncthreads();
            {   // stage weight slab (dz, icc)
                const uint4* sh = (const uint4*)(g_w2h + (dz * 2 + icc) * 2880);
                const uint4* sl = (const uint4*)(g_w2l + (dz * 2 + icc) * 2880);
                uint4* dh = (uint4*)swh; uint4* dl = (uint4*)swl;
                for (int i = tid; i < 720; i += 256) { dh[i] = sh[i]; dl[i] = sl[i]; }
            }
            __syncthreads();
            #pragma unroll
            for (int dy = 0; dy < 3; dy++)
            #pragma unroll
            for (int dx = 0; dx < 3; dx++) {
                const int t = dy * 3 + dx;
                u32 ah[2][4], al[2][4];
                #pragma unroll
                for (int ks = 0; ks < 2; ks++) {
                    int base = t * 320 + g * 20 + ks * 8;
                    ah[ks][0] = swh[base + tig];       ah[ks][1] = swh[base + 160 + tig];
                    ah[ks][2] = swh[base + 4 + tig];   ah[ks][3] = swh[base + 164 + tig];
                    al[ks][0] = swl[base + tig];       al[ks][1] = swl[base + 160 + tig];
                    al[ks][2] = swl[base + 4 + tig];   al[ks][3] = swl[base + 164 + tig];
                }
                #pragma unroll
                for (int ni = 0; ni < 2; ni++) {
                    int nt = warp * 2 + ni;
                    int h = (((nt >> 3) + dz) * 10 + (nt & 7) + dy) * 10 + g + dx;
                    #pragma unroll
                    for (int ks = 0; ks < 2; ks++) {
                        u32 bh0 = sbh[(ks * 8 + tig) * AW + h];
                        u32 bh1 = sbh[(ks * 8 + tig + 4) * AW + h];
                        u32 bl0 = sbl[(ks * 8 + tig) * AW + h];
                        u32 bl1 = sbl[(ks * 8 + tig + 4) * AW + h];
                        mma16(d[ni], ah[ks], bh0, bh1);
                        mma16(d[ni], ah[ks], bl0, bl1);
                        mma16(d[ni], al[ks], bh0, bh1);
                    }
                }
            }
        }
    }

    // epilogue: y += (d + b2)*dt + sdt*noise   (oc = g and g+8; vox = 2tig,2tig+1)
    const float dt = 0.05f, sdt = 0.1f * 0.22360680f;
    const float bb0 = b2[g], bb1 = b2[g + 8];
    #pragma unroll
    for (int ni = 0; ni < 2; ni++) {
        int nt = warp * 2 + ni;
        int gvox = ((z0 + (nt >> 3)) * SS + (y0 + (nt & 7))) * SS + x0 + 2 * tig;
        int b0 = g * S3 + gvox, b1i = (g + 8) * S3 + gvox;
        float2 y0v = *(const float2*)&y[b0];
        float2 y1v = *(const float2*)&y[b1i];
        float2 n0v = *(const float2*)&noise[b0];
        float2 n1v = *(const float2*)&noise[b1i];
        y0v.x += (d[ni][0] + bb0) * dt + sdt * n0v.x;
        y0v.y += (d[ni][1] + bb0) * dt + sdt * n0v.y;
        y1v.x += (d[ni][2] + bb1) * dt + sdt * n1v.x;
        y1v.y += (d[ni][3] + bb1) * dt + sdt * n1v.y;
        *(float2*)&y[b0] = y0v;
        *(float2*)&y[b1i] = y1v;
    }
}

// ---------------------------------------------------------------------------
extern "C" void kernel_launch(void* const* d_in, const int* in_sizes, int n_in,
                              void* d_out, int out_size) {
    const float* x     = (const float*)d_in[0];
    const float* w1    = (const float*)d_in[2];
    const float* b1    = (const float*)d_in[3];
    const float* w2    = (const float*)d_in[4];
    const float* b2    = (const float*)d_in[5];
    const float* noise = (const float*)d_in[6];
    float* y = (float*)d_out;

    const size_t smA = 20352 * sizeof(u32);   // 81.4 KB
    const size_t smB = 18816 * sizeof(u32);   // 75.3 KB
    cudaFuncSetAttribute(conv1_mma, cudaFuncAttributeMaxDynamicSharedMemorySize, (int)smA);
    cudaFuncSetAttribute(conv2_mma, cudaFuncAttributeMaxDynamicSharedMemorySize, (int)smB);

    cudaMemcpyAsync(y, x, (size_t)16 * S3 * sizeof(float), cudaMemcpyDeviceToDevice);
    prep_w1<<<(27 * 64 * 24 + 255) / 256, 256>>>(w1);
    prep_w2<<<(3 * 2 * 9 * 16 * 40 + 255) / 256, 256>>>(w2);

    dim3 gC(8, 8, 32);   // x/8, y/8, z/2 = 2048 CTAs
    for (int step = 0; step < 20; step++) {
        conv1_mma<<<gC, 256, smA>>>(y, b1);
        conv2_mma<<<gC, 256, smB>>>(y, b2, noise + (size_t)step * 16 * S3);
    }
}